// round 4
// baseline (speedup 1.0000x reference)
#include <cuda_runtime.h>
#include <cstdint>

// Problem constants (fixed by the dataset)
#define N_NODES 50000
#define NPAD    50048            // 391 * 128
#define N_EDGES 800000
#define D       128
#define NGRAPH  256
#define OUTF    256
#define N_TILES (NPAD / 128)     // 391

// ---------------- device scratch (no allocations allowed) ----------------
__device__ float    g_hA[(size_t)NPAD * D];
__device__ float    g_hB[(size_t)NPAD * D];
__device__ int      g_counts [N_NODES];
__device__ int      g_offsets[N_NODES + 1];
__device__ int      g_cursor [N_NODES];
__device__ int      g_esrc   [N_EDGES];
__device__ float    g_gsum[NGRAPH * D];
__device__ unsigned g_gmax[NGRAPH * D];
__device__ int      g_gcnt[NGRAPH];

// ---------------- init: zero accumulators & degree counts ----------------
__global__ void zero_kernel() {
    int i = blockIdx.x * blockDim.x + threadIdx.x;
    if (i < N_NODES) g_counts[i] = 0;
    if (i < NGRAPH * D) { g_gsum[i] = 0.f; g_gmax[i] = 0u; }
    if (i < NGRAPH) g_gcnt[i] = 0;
}

// ---------------- CSR build (bucket edges by dst) ----------------
__global__ void count_kernel(const int* __restrict__ ei) {
    int e = blockIdx.x * blockDim.x + threadIdx.x;
    if (e < N_EDGES) atomicAdd(&g_counts[ei[N_EDGES + e]], 1);
}

// single-block exclusive scan over 50000 counts (chunks of 1024)
__global__ void scan_kernel() {
    __shared__ int sh[1024];
    int t = threadIdx.x;
    int carry = 0;
    for (int base = 0; base < N_NODES; base += 1024) {
        int idx = base + t;
        int v = (idx < N_NODES) ? g_counts[idx] : 0;
        sh[t] = v;
        __syncthreads();
        for (int off = 1; off < 1024; off <<= 1) {
            int y = (t >= off) ? sh[t - off] : 0;
            __syncthreads();
            sh[t] += y;
            __syncthreads();
        }
        int incl = sh[t];
        int total = sh[1023];
        int excl = carry + incl - v;
        if (idx < N_NODES) {
            g_offsets[idx] = excl;
            g_cursor[idx]  = excl;
        }
        carry += total;
        __syncthreads();
    }
    if (t == 0) g_offsets[N_NODES] = carry;
}

__global__ void fill_kernel(const int* __restrict__ ei) {
    int e = blockIdx.x * blockDim.x + threadIdx.x;
    if (e < N_EDGES) {
        int d = ei[N_EDGES + e];
        int p = atomicAdd(&g_cursor[d], 1);
        g_esrc[p] = ei[e];
    }
}

// ---------------- tf32 tensor-core helpers (3xTF32 split for ~fp32 accuracy) ----
__device__ __forceinline__ unsigned f2tf(float f) {
    unsigned r;
    asm("cvt.rna.tf32.f32 %0, %1;" : "=r"(r) : "f"(f));
    return r;
}
__device__ __forceinline__ void split_tf32(float v, unsigned& hi, unsigned& lo) {
    hi = f2tf(v);
    lo = f2tf(v - __uint_as_float(hi));
}
__device__ __forceinline__ void mma8(float c[4],
                                     unsigned a0, unsigned a1, unsigned a2, unsigned a3,
                                     unsigned b0, unsigned b1) {
    asm volatile(
        "mma.sync.aligned.m16n8k8.row.col.f32.tf32.tf32.f32 "
        "{%0,%1,%2,%3}, {%4,%5,%6,%7}, {%8,%9}, {%0,%1,%2,%3};"
        : "+f"(c[0]), "+f"(c[1]), "+f"(c[2]), "+f"(c[3])
        : "r"(a0), "r"(a1), "r"(a2), "r"(a3), "r"(b0), "r"(b1));
}

// 128x128x128 GEMM tile: c += Zs(128x128, stride 132) @ Ws(128x128, stride 132)
// 8 warps as 2x4 (wm,wn). Warp tile 64x32 = 4x4 m16n8 fragments.
__device__ __forceinline__ void gemm_tile(const float* __restrict__ Zs,
                                          const float* __restrict__ Ws,
                                          float c[4][4][4],
                                          int wm, int wn, int g, int tg) {
#pragma unroll 2
    for (int ks = 0; ks < 16; ks++) {
        const int k0 = ks * 8;
        unsigned ah[4][4], al[4][4];
#pragma unroll
        for (int mf = 0; mf < 4; mf++) {
            const float* p = &Zs[(wm * 64 + mf * 16 + g) * 132 + k0 + tg];
            float x0 = p[0];
            float x1 = p[8 * 132];
            float x2 = p[4];
            float x3 = p[8 * 132 + 4];
            split_tf32(x0, ah[mf][0], al[mf][0]);
            split_tf32(x1, ah[mf][1], al[mf][1]);
            split_tf32(x2, ah[mf][2], al[mf][2]);
            split_tf32(x3, ah[mf][3], al[mf][3]);
        }
        unsigned bh[4][2], bl[4][2];
#pragma unroll
        for (int nf = 0; nf < 4; nf++) {
            int cB = wn * 32 + nf * 8 + g;
            float y0 = Ws[(k0 + tg) * 132 + cB];
            float y1 = Ws[(k0 + tg + 4) * 132 + cB];
            split_tf32(y0, bh[nf][0], bl[nf][0]);
            split_tf32(y1, bh[nf][1], bl[nf][1]);
        }
#pragma unroll
        for (int mf = 0; mf < 4; mf++)
#pragma unroll
            for (int nf = 0; nf < 4; nf++) {
                mma8(c[mf][nf], al[mf][0], al[mf][1], al[mf][2], al[mf][3],
                     bh[nf][0], bh[nf][1]);
                mma8(c[mf][nf], ah[mf][0], ah[mf][1], ah[mf][2], ah[mf][3],
                     bl[nf][0], bl[nf][1]);
                mma8(c[mf][nf], ah[mf][0], ah[mf][1], ah[mf][2], ah[mf][3],
                     bh[nf][0], bh[nf][1]);
            }
    }
}

// ---------------- fused GIN layer:  hout = relu(relu((h + agg) @ W1) @ W2) ----
// One block = 128 consecutive node rows. Aggregation gathers straight into SMEM.
__global__ __launch_bounds__(256, 1)
void gin_layer_kernel(const float* __restrict__ xin, int sel,
                      const float* __restrict__ w1, const float* __restrict__ w2,
                      int outsel) {
    extern __shared__ float sm[];
    float* Zs = sm;                 // [128][132]
    float* Ws = sm + 128 * 132;     // [128][132]
    const float* hin = (sel == 0) ? xin : ((sel == 1) ? g_hA : g_hB);
    float* hout = (outsel == 1) ? g_hA : g_hB;

    const int tid = threadIdx.x;
    const int lane = tid & 31;
    const int warp = tid >> 5;
    const int row0 = blockIdx.x * 128;

    // ---- aggregation: 16 rows per warp, one float4 per lane, into Zs ----
    const float4* h4 = (const float4*)hin;
#pragma unroll 1
    for (int i = 0; i < 16; i++) {
        int r = warp * 16 + i;
        int node = row0 + r;
        float4 acc = make_float4(0.f, 0.f, 0.f, 0.f);
        if (node < N_NODES) {
            acc = h4[(size_t)node * 32 + lane];
            int s = g_offsets[node];
            int e = g_offsets[node + 1];
            int j = s;
            for (; j + 4 <= e; j += 4) {
                int s0 = g_esrc[j], s1 = g_esrc[j + 1];
                int s2 = g_esrc[j + 2], s3 = g_esrc[j + 3];
                float4 v0 = h4[(size_t)s0 * 32 + lane];
                float4 v1 = h4[(size_t)s1 * 32 + lane];
                float4 v2 = h4[(size_t)s2 * 32 + lane];
                float4 v3 = h4[(size_t)s3 * 32 + lane];
                acc.x += v0.x + v1.x + v2.x + v3.x;
                acc.y += v0.y + v1.y + v2.y + v3.y;
                acc.z += v0.z + v1.z + v2.z + v3.z;
                acc.w += v0.w + v1.w + v2.w + v3.w;
            }
            for (; j < e; j++) {
                int s0 = g_esrc[j];
                float4 v0 = h4[(size_t)s0 * 32 + lane];
                acc.x += v0.x; acc.y += v0.y; acc.z += v0.z; acc.w += v0.w;
            }
        }
        *(float4*)&Zs[r * 132 + lane * 4] = acc;
    }
    // ---- Ws <- W1 (row-major [k][n]) ----
    {
        const float4* w4 = (const float4*)w1;
#pragma unroll
        for (int i = 0; i < 16; i++) {
            int q = tid + i * 256;
            int k = q >> 5, cc = (q & 31) * 4;
            *(float4*)&Ws[k * 132 + cc] = w4[q];
        }
    }
    __syncthreads();

    const int g = lane >> 2, tg = lane & 3;
    const int wm = warp >> 2, wn = warp & 3;

    float c[4][4][4];
#pragma unroll
    for (int mf = 0; mf < 4; mf++)
#pragma unroll
        for (int nf = 0; nf < 4; nf++)
#pragma unroll
            for (int q = 0; q < 4; q++) c[mf][nf][q] = 0.f;

    gemm_tile(Zs, Ws, c, wm, wn, g, tg);
    __syncthreads();

    // ---- relu(t) -> Zs ; Ws <- W2 ----
#pragma unroll
    for (int mf = 0; mf < 4; mf++)
#pragma unroll
        for (int nf = 0; nf < 4; nf++) {
            int R = wm * 64 + mf * 16 + g;
            int C0 = wn * 32 + nf * 8 + 2 * tg;
            float2 v01, v23;
            v01.x = fmaxf(c[mf][nf][0], 0.f);
            v01.y = fmaxf(c[mf][nf][1], 0.f);
            v23.x = fmaxf(c[mf][nf][2], 0.f);
            v23.y = fmaxf(c[mf][nf][3], 0.f);
            *(float2*)&Zs[R * 132 + C0] = v01;
            *(float2*)&Zs[(R + 8) * 132 + C0] = v23;
        }
    {
        const float4* w4 = (const float4*)w2;
#pragma unroll
        for (int i = 0; i < 16; i++) {
            int q = tid + i * 256;
            int k = q >> 5, cc = (q & 31) * 4;
            *(float4*)&Ws[k * 132 + cc] = w4[q];
        }
    }
    __syncthreads();

#pragma unroll
    for (int mf = 0; mf < 4; mf++)
#pragma unroll
        for (int nf = 0; nf < 4; nf++)
#pragma unroll
            for (int q = 0; q < 4; q++) c[mf][nf][q] = 0.f;

    gemm_tile(Zs, Ws, c, wm, wn, g, tg);

    // ---- relu -> gmem ----
#pragma unroll
    for (int mf = 0; mf < 4; mf++)
#pragma unroll
        for (int nf = 0; nf < 4; nf++) {
            int R = row0 + wm * 64 + mf * 16 + g;
            int C0 = wn * 32 + nf * 8 + 2 * tg;
            float2 v01, v23;
            v01.x = fmaxf(c[mf][nf][0], 0.f);
            v01.y = fmaxf(c[mf][nf][1], 0.f);
            v23.x = fmaxf(c[mf][nf][2], 0.f);
            v23.y = fmaxf(c[mf][nf][3], 0.f);
            *(float2*)&hout[(size_t)R * D + C0] = v01;
            *(float2*)&hout[(size_t)(R + 8) * D + C0] = v23;
        }
}

// ---------------- pooling: segmented reduction exploiting sorted batch ----------
// One block = 128 consecutive nodes; thread t = feature t. One atomic per
// (graph-boundary x feature) instead of per (node x feature).
__global__ __launch_bounds__(128)
void pool_kernel(const int* __restrict__ batch) {
    int f = threadIdx.x;
    int n0 = blockIdx.x * 128;
    float s = 0.f, m = 0.f;
    int cur = -1, cnt = 0;
    for (int i = 0; i < 128; i++) {
        int n = n0 + i;
        if (n >= N_NODES) break;
        int gg = batch[n];
        if (gg != cur) {
            if (cur >= 0) {
                atomicAdd(&g_gsum[cur * D + f], s);
                atomicMax(&g_gmax[cur * D + f], __float_as_uint(m));  // h >= 0
                if (f == 0) atomicAdd(&g_gcnt[cur], cnt);
            }
            cur = gg; s = 0.f; m = 0.f; cnt = 0;
        }
        float v = g_hA[(size_t)n * D + f];
        s += v;
        m = fmaxf(m, v);
        cnt++;
    }
    if (cur >= 0) {
        atomicAdd(&g_gsum[cur * D + f], s);
        atomicMax(&g_gmax[cur * D + f], __float_as_uint(m));
        if (f == 0) atomicAdd(&g_gcnt[cur], cnt);
    }
}

// ---------------- readout: [gmax | gmean | gsum] @ out_w + out_b ----------------
__global__ void readout_kernel(const float* __restrict__ ow,
                               const float* __restrict__ ob,
                               float* __restrict__ out) {
    __shared__ float p[3 * D];
    int g = blockIdx.x;
    int o = threadIdx.x;
    if (o < D) {
        float s = g_gsum[g * D + o];
        float cn = fmaxf((float)g_gcnt[g], 1.f);
        p[o]         = __uint_as_float(g_gmax[g * D + o]);
        p[D + o]     = s / cn;
        p[2 * D + o] = s;
    }
    __syncthreads();
    float acc = ob[o];
#pragma unroll 8
    for (int f = 0; f < 3 * D; f++) acc = fmaf(p[f], ow[f * OUTF + o], acc);
    out[g * OUTF + o] = acc;
}

// ---------------- launch ----------------
extern "C" void kernel_launch(void* const* d_in, const int* in_sizes, int n_in,
                              void* d_out, int out_size) {
    const float* x      = (const float*)d_in[0];
    const int*   ei     = (const int*)  d_in[1];
    const int*   batch  = (const int*)  d_in[2];
    const float* w1_0   = (const float*)d_in[3];
    const float* w2_0   = (const float*)d_in[4];
    const float* gin_w1 = (const float*)d_in[5];   // [2][128][128]
    const float* gin_w2 = (const float*)d_in[6];
    const float* out_w  = (const float*)d_in[7];   // [384][256]
    const float* out_b  = (const float*)d_in[8];
    float* out = (float*)d_out;

    const int SMEM = 2 * 128 * 132 * 4;  // 135168 B
    cudaFuncSetAttribute(gin_layer_kernel,
                         cudaFuncAttributeMaxDynamicSharedMemorySize, SMEM);

    // init + CSR build
    zero_kernel<<<(N_NODES + 255) / 256, 256>>>();
    count_kernel<<<(N_EDGES + 255) / 256, 256>>>(ei);
    scan_kernel<<<1, 1024>>>();
    fill_kernel<<<(N_EDGES + 255) / 256, 256>>>(ei);

    // fused layers (agg + 2 GEMMs + relus per launch)
    gin_layer_kernel<<<N_TILES, 256, SMEM>>>(x, 0, w1_0, w2_0, 1);
    gin_layer_kernel<<<N_TILES, 256, SMEM>>>(x, 1, gin_w1, gin_w2, 2);
    gin_layer_kernel<<<N_TILES, 256, SMEM>>>(x, 2, gin_w1 + 128 * 128,
                                             gin_w2 + 128 * 128, 1);

    // pooling + readout
    pool_kernel<<<N_TILES, 128>>>(batch);
    readout_kernel<<<NGRAPH, 256>>>(out_w, out_b, out);
}

// round 6
// speedup vs baseline: 1.1464x; 1.1464x over previous
#include <cuda_runtime.h>
#include <cuda_fp16.h>
#include <cstdint>

// Problem constants (fixed by the dataset)
#define N_NODES 50000
#define NPAD    50048            // 391 * 128
#define N_EDGES 800000
#define D       128
#define NGRAPH  256
#define OUTF    256
#define N_TILES (NPAD / 128)     // 391

// ---------------- device scratch (no allocations allowed) ----------------
__device__ float    g_hA[(size_t)NPAD * D];
__device__ float    g_hB[(size_t)NPAD * D];
__device__ float    g_z [(size_t)NPAD * D];
__device__ int      g_counts [N_NODES];
__device__ int      g_offsets[N_NODES + 1];
__device__ int      g_cursor [N_NODES];
__device__ int      g_esrc   [N_EDGES];
__device__ float    g_gsum[NGRAPH * D];
__device__ unsigned g_gmax[NGRAPH * D];
__device__ int      g_gcnt[NGRAPH];

// ---------------- init ----------------
__global__ void zero_kernel() {
    int i = blockIdx.x * blockDim.x + threadIdx.x;
    if (i < N_NODES) g_counts[i] = 0;
    if (i < NGRAPH * D) { g_gsum[i] = 0.f; g_gmax[i] = 0u; }
    if (i < NGRAPH) g_gcnt[i] = 0;
}

// ---------------- CSR build (bucket edges by dst) ----------------
__global__ void count_kernel(const int* __restrict__ ei) {
    int e = blockIdx.x * blockDim.x + threadIdx.x;
    if (e < N_EDGES) atomicAdd(&g_counts[ei[N_EDGES + e]], 1);
}

__global__ void scan_kernel() {
    __shared__ int sh[1024];
    int t = threadIdx.x;
    int carry = 0;
    for (int base = 0; base < N_NODES; base += 1024) {
        int idx = base + t;
        int v = (idx < N_NODES) ? g_counts[idx] : 0;
        sh[t] = v;
        __syncthreads();
        for (int off = 1; off < 1024; off <<= 1) {
            int y = (t >= off) ? sh[t - off] : 0;
            __syncthreads();
            sh[t] += y;
            __syncthreads();
        }
        int incl = sh[t];
        int total = sh[1023];
        int excl = carry + incl - v;
        if (idx < N_NODES) { g_offsets[idx] = excl; g_cursor[idx] = excl; }
        carry += total;
        __syncthreads();
    }
    if (t == 0) g_offsets[N_NODES] = carry;
}

__global__ void fill_kernel(const int* __restrict__ ei) {
    int e = blockIdx.x * blockDim.x + threadIdx.x;
    if (e < N_EDGES) {
        int d = ei[N_EDGES + e];
        int p = atomicAdd(&g_cursor[d], 1);
        g_esrc[p] = ei[e];
    }
}

// ---------------- aggregation: g_z[i] = h[i] + sum_{CSR[i]} h[src] ----------
__global__ void agg_kernel(const float* __restrict__ xin, int sel) {
    const float* hin = (sel == 0) ? xin : ((sel == 1) ? g_hA : g_hB);
    int w    = (blockIdx.x * blockDim.x + threadIdx.x) >> 5;
    int lane = threadIdx.x & 31;
    if (w >= NPAD) return;
    float4 acc = make_float4(0.f, 0.f, 0.f, 0.f);
    if (w < N_NODES) {
        const float4* h4 = (const float4*)hin;
        acc = h4[(size_t)w * 32 + lane];
        int s = g_offsets[w];
        int e = g_offsets[w + 1];
        int j = s;
        for (; j + 4 <= e; j += 4) {
            int s0 = g_esrc[j], s1 = g_esrc[j + 1], s2 = g_esrc[j + 2], s3 = g_esrc[j + 3];
            float4 v0 = h4[(size_t)s0 * 32 + lane];
            float4 v1 = h4[(size_t)s1 * 32 + lane];
            float4 v2 = h4[(size_t)s2 * 32 + lane];
            float4 v3 = h4[(size_t)s3 * 32 + lane];
            acc.x += v0.x + v1.x + v2.x + v3.x;
            acc.y += v0.y + v1.y + v2.y + v3.y;
            acc.z += v0.z + v1.z + v2.z + v3.z;
            acc.w += v0.w + v1.w + v2.w + v3.w;
        }
        for (; j < e; j++) {
            int s0 = g_esrc[j];
            float4 v0 = h4[(size_t)s0 * 32 + lane];
            acc.x += v0.x; acc.y += v0.y; acc.z += v0.z; acc.w += v0.w;
        }
    }
    ((float4*)g_z)[(size_t)w * 32 + lane] = acc;
}

// ---------------- fp16-split tensor-core MLP --------------------------------
// hout = relu( relu(z @ W1) @ W2 ), exact-ish via 2-way fp16 split, 3 products.
// SMEM: Ah/Al (A hi/lo, [128][136] fp16) + Bh/Bl (B^T hi/lo, [128][136] fp16).
// Row stride 68 u32 == 4 (mod 32) -> all fragment LDS are bank-conflict-free.

#define STRH 136   // fp16 per row
#define STRW 68    // u32 per row
#define OFF_AH 0
#define OFF_AL (128 * STRH * 2)
#define OFF_BH (2 * 128 * STRH * 2)
#define OFF_BL (3 * 128 * STRH * 2)
#define SMEM_MLP (4 * 128 * STRH * 2)   // 139264 B

__device__ __forceinline__ void fsplit(float v, __half& hi, __half& lo) {
    hi = __float2half_rn(v);
    lo = __float2half_rn(v - __half2float(hi));
}
__device__ __forceinline__ unsigned pack2(__half a, __half b) {
    union { __half2 h; unsigned u; } q;
    q.h = __halves2half2(a, b);
    return q.u;
}
__device__ __forceinline__ void mma16(float c[4],
                                      unsigned a0, unsigned a1, unsigned a2, unsigned a3,
                                      unsigned b0, unsigned b1) {
    asm volatile(
        "mma.sync.aligned.m16n8k16.row.col.f32.f16.f16.f32 "
        "{%0,%1,%2,%3}, {%4,%5,%6,%7}, {%8,%9}, {%0,%1,%2,%3};"
        : "+f"(c[0]), "+f"(c[1]), "+f"(c[2]), "+f"(c[3])
        : "r"(a0), "r"(a1), "r"(a2), "r"(a3), "r"(b0), "r"(b1));
}

// 128x128x128: c += A(hi+lo) @ B(hi+lo)^T dropping lo*lo.
__device__ __forceinline__ void gemm128(const unsigned* __restrict__ Ah,
                                        const unsigned* __restrict__ Al,
                                        const unsigned* __restrict__ Bh,
                                        const unsigned* __restrict__ Bl,
                                        float c[4][4][4], int wm, int wn, int lane) {
    const int g = lane >> 2, tq = lane & 3;
#pragma unroll
    for (int ks = 0; ks < 8; ks++) {
        const int kq = ks * 8 + tq;           // u32 col index
        unsigned ah[4][4], al[4][4];
#pragma unroll
        for (int mf = 0; mf < 4; mf++) {
            int b = (wm * 64 + mf * 16 + g) * STRW + kq;
            ah[mf][0] = Ah[b];            ah[mf][1] = Ah[b + 8 * STRW];
            ah[mf][2] = Ah[b + 4];        ah[mf][3] = Ah[b + 8 * STRW + 4];
            al[mf][0] = Al[b];            al[mf][1] = Al[b + 8 * STRW];
            al[mf][2] = Al[b + 4];        al[mf][3] = Al[b + 8 * STRW + 4];
        }
        unsigned bh[4][2], bl[4][2];
#pragma unroll
        for (int nf = 0; nf < 4; nf++) {
            int b = (wn * 32 + nf * 8 + g) * STRW + kq;
            bh[nf][0] = Bh[b];  bh[nf][1] = Bh[b + 4];
            bl[nf][0] = Bl[b];  bl[nf][1] = Bl[b + 4];
        }
#pragma unroll
        for (int mf = 0; mf < 4; mf++)
#pragma unroll
            for (int nf = 0; nf < 4; nf++) {
                mma16(c[mf][nf], ah[mf][0], ah[mf][1], ah[mf][2], ah[mf][3],
                      bh[nf][0], bh[nf][1]);
                mma16(c[mf][nf], ah[mf][0], ah[mf][1], ah[mf][2], ah[mf][3],
                      bl[nf][0], bl[nf][1]);
                mma16(c[mf][nf], al[mf][0], al[mf][1], al[mf][2], al[mf][3],
                      bh[nf][0], bh[nf][1]);
            }
    }
}

// Transpose-split W[k][n] -> B[n][k] hi/lo (one-time per tile, per GEMM).
__device__ __forceinline__ void load_w(const float* __restrict__ W,
                                       __half* Bh16, __half* Bl16, int tid) {
    const float4* wv = (const float4*)W;
#pragma unroll
    for (int i = 0; i < 16; i++) {
        int idx = tid + i * 256;
        int k = idx >> 5, n4 = (idx & 31) * 4;
        float4 v = wv[idx];
        __half h, l;
        fsplit(v.x, h, l); Bh16[(n4 + 0) * STRH + k] = h; Bl16[(n4 + 0) * STRH + k] = l;
        fsplit(v.y, h, l); Bh16[(n4 + 1) * STRH + k] = h; Bl16[(n4 + 1) * STRH + k] = l;
        fsplit(v.z, h, l); Bh16[(n4 + 2) * STRH + k] = h; Bl16[(n4 + 2) * STRH + k] = l;
        fsplit(v.w, h, l); Bh16[(n4 + 3) * STRH + k] = h; Bl16[(n4 + 3) * STRH + k] = l;
    }
}

__global__ __launch_bounds__(256)
void gin_mlp(const float* __restrict__ w1, const float* __restrict__ w2, int outsel) {
    extern __shared__ char smc[];
    unsigned* Ah = (unsigned*)(smc + OFF_AH);
    unsigned* Al = (unsigned*)(smc + OFF_AL);
    unsigned* Bh = (unsigned*)(smc + OFF_BH);
    unsigned* Bl = (unsigned*)(smc + OFF_BL);
    float* hout = (outsel == 1) ? g_hA : g_hB;
    const float* zin = g_z + (size_t)blockIdx.x * 128 * D;

    const int tid = threadIdx.x;
    const int lane = tid & 31;
    const int warp = tid >> 5;
    const int wm = warp >> 2, wn = warp & 3;
    const int g = lane >> 2, tq = lane & 3;

    // ---- split A (z tile) once ----
    {
        const float4* z4 = (const float4*)zin;
#pragma unroll
        for (int i = 0; i < 16; i++) {
            int idx = tid + i * 256;
            int r = idx >> 5, cu = (idx & 31) * 2;   // u32 col
            float4 v = z4[idx];
            __half h0, l0, h1, l1, h2, l2, h3, l3;
            fsplit(v.x, h0, l0); fsplit(v.y, h1, l1);
            fsplit(v.z, h2, l2); fsplit(v.w, h3, l3);
            Ah[r * STRW + cu]     = pack2(h0, h1);
            Ah[r * STRW + cu + 1] = pack2(h2, h3);
            Al[r * STRW + cu]     = pack2(l0, l1);
            Al[r * STRW + cu + 1] = pack2(l2, l3);
        }
    }
    load_w(w1, (__half*)Bh, (__half*)Bl, tid);
    __syncthreads();

    float c[4][4][4];
#pragma unroll
    for (int mf = 0; mf < 4; mf++)
#pragma unroll
        for (int nf = 0; nf < 4; nf++)
#pragma unroll
            for (int q = 0; q < 4; q++) c[mf][nf][q] = 0.f;

    gemm128(Ah, Al, Bh, Bl, c, wm, wn, lane);
    __syncthreads();

    // ---- t = relu(.) split straight back into Ah/Al; W2 into Bh/Bl ----
#pragma unroll
    for (int mf = 0; mf < 4; mf++)
#pragma unroll
        for (int nf = 0; nf < 4; nf++) {
            int r  = wm * 64 + mf * 16 + g;
            int cu = wn * 16 + nf * 4 + tq;          // u32 col of (c, c+1)
            float v0 = fmaxf(c[mf][nf][0], 0.f), v1 = fmaxf(c[mf][nf][1], 0.f);
            float v2 = fmaxf(c[mf][nf][2], 0.f), v3 = fmaxf(c[mf][nf][3], 0.f);
            __half h0, l0, h1, l1, h2, l2, h3, l3;
            fsplit(v0, h0, l0); fsplit(v1, h1, l1);
            fsplit(v2, h2, l2); fsplit(v3, h3, l3);
            Ah[r * STRW + cu]       = pack2(h0, h1);
            Al[r * STRW + cu]       = pack2(l0, l1);
            Ah[(r + 8) * STRW + cu] = pack2(h2, h3);
            Al[(r + 8) * STRW + cu] = pack2(l2, l3);
        }
    load_w(w2, (__half*)Bh, (__half*)Bl, tid);
    __syncthreads();

#pragma unroll
    for (int mf = 0; mf < 4; mf++)
#pragma unroll
        for (int nf = 0; nf < 4; nf++)
#pragma unroll
            for (int q = 0; q < 4; q++) c[mf][nf][q] = 0.f;

    gemm128(Ah, Al, Bh, Bl, c, wm, wn, lane);

    // ---- relu -> gmem ----
    const size_t row0 = (size_t)blockIdx.x * 128;
#pragma unroll
    for (int mf = 0; mf < 4; mf++)
#pragma unroll
        for (int nf = 0; nf < 4; nf++) {
            int r  = wm * 64 + mf * 16 + g;
            int cc = wn * 32 + nf * 8 + tq * 2;
            float2 o0, o1;
            o0.x = fmaxf(c[mf][nf][0], 0.f); o0.y = fmaxf(c[mf][nf][1], 0.f);
            o1.x = fmaxf(c[mf][nf][2], 0.f); o1.y = fmaxf(c[mf][nf][3], 0.f);
            *(float2*)&hout[(row0 + r) * D + cc]     = o0;
            *(float2*)&hout[(row0 + r + 8) * D + cc] = o1;
        }
}

// ---------------- pooling: segmented reduction exploiting sorted batch ----------
__global__ __launch_bounds__(128)
void pool_kernel(const int* __restrict__ batch) {
    int f = threadIdx.x;
    int n0 = blockIdx.x * 128;
    float s = 0.f, m = 0.f;
    int cur = -1, cnt = 0;
    for (int i = 0; i < 128; i++) {
        int n = n0 + i;
        if (n >= N_NODES) break;
        int gg = batch[n];
        if (gg != cur) {
            if (cur >= 0) {
                atomicAdd(&g_gsum[cur * D + f], s);
                atomicMax(&g_gmax[cur * D + f], __float_as_uint(m));  // h >= 0
                if (f == 0) atomicAdd(&g_gcnt[cur], cnt);
            }
            cur = gg; s = 0.f; m = 0.f; cnt = 0;
        }
        float v = g_hA[(size_t)n * D + f];
        s += v;
        m = fmaxf(m, v);
        cnt++;
    }
    if (cur >= 0) {
        atomicAdd(&g_gsum[cur * D + f], s);
        atomicMax(&g_gmax[cur * D + f], __float_as_uint(m));
        if (f == 0) atomicAdd(&g_gcnt[cur], cnt);
    }
}

// ---------------- readout: [gmax | gmean | gsum] @ out_w + out_b ----------------
__global__ void readout_kernel(const float* __restrict__ ow,
                               const float* __restrict__ ob,
                               float* __restrict__ out) {
    __shared__ float p[3 * D];
    int g = blockIdx.x;
    int o = threadIdx.x;
    if (o < D) {
        float s = g_gsum[g * D + o];
        float cn = fmaxf((float)g_gcnt[g], 1.f);
        p[o]         = __uint_as_float(g_gmax[g * D + o]);
        p[D + o]     = s / cn;
        p[2 * D + o] = s;
    }
    __syncthreads();
    float acc = ob[o];
#pragma unroll 8
    for (int f = 0; f < 3 * D; f++) acc = fmaf(p[f], ow[f * OUTF + o], acc);
    out[g * OUTF + o] = acc;
}

// ---------------- launch ----------------
extern "C" void kernel_launch(void* const* d_in, const int* in_sizes, int n_in,
                              void* d_out, int out_size) {
    const float* x      = (const float*)d_in[0];
    const int*   ei     = (const int*)  d_in[1];
    const int*   batch  = (const int*)  d_in[2];
    const float* w1_0   = (const float*)d_in[3];
    const float* w2_0   = (const float*)d_in[4];
    const float* gin_w1 = (const float*)d_in[5];   // [2][128][128]
    const float* gin_w2 = (const float*)d_in[6];
    const float* out_w  = (const float*)d_in[7];   // [384][256]
    const float* out_b  = (const float*)d_in[8];
    float* out = (float*)d_out;

    cudaFuncSetAttribute(gin_mlp,
                         cudaFuncAttributeMaxDynamicSharedMemorySize, SMEM_MLP);

    // init + CSR build
    zero_kernel<<<(N_NODES + 255) / 256, 256>>>();
    count_kernel<<<(N_EDGES + 255) / 256, 256>>>(ei);
    scan_kernel<<<1, 1024>>>();
    fill_kernel<<<(N_EDGES + 255) / 256, 256>>>(ei);

    const int AGG_BLOCKS = NPAD / 8;  // 8 warps/block, 1 warp/node

    // layer 0: x -> hA
    agg_kernel<<<AGG_BLOCKS, 256>>>(x, 0);
    gin_mlp<<<N_TILES, 256, SMEM_MLP>>>(w1_0, w2_0, 1);
    // layer 1: hA -> hB
    agg_kernel<<<AGG_BLOCKS, 256>>>(x, 1);
    gin_mlp<<<N_TILES, 256, SMEM_MLP>>>(gin_w1, gin_w2, 2);
    // layer 2: hB -> hA
    agg_kernel<<<AGG_BLOCKS, 256>>>(x, 2);
    gin_mlp<<<N_TILES, 256, SMEM_MLP>>>(gin_w1 + 128 * 128,
                                        gin_w2 + 128 * 128, 1);

    // pooling + readout
    pool_kernel<<<N_TILES, 128>>>(batch);
    readout_kernel<<<NGRAPH, 256>>>(out_w, out_b, out);
}

// round 7
// speedup vs baseline: 1.3186x; 1.1502x over previous
#include <cuda_runtime.h>
#include <cuda_fp16.h>
#include <cstdint>

// Problem constants (fixed by the dataset)
#define N_NODES 50000
#define NPAD    50048            // 391 * 128
#define N_EDGES 800000
#define D       128
#define NGRAPH  256
#define OUTF    256
#define N_TILES (NPAD / 128)     // 391

// ---------------- device scratch (no allocations allowed) ----------------
__device__ float    g_hA[(size_t)NPAD * D];
__device__ float    g_hB[(size_t)NPAD * D];
__device__ float    g_z [(size_t)NPAD * D];
__device__ int      g_counts [N_NODES];
__device__ int      g_offsets[N_NODES];      // segment starts (not monotonic)
__device__ int      g_cursor [N_NODES];
__device__ int      g_esrc   [N_EDGES];
__device__ int      g_total;
__device__ float    g_gsum[NGRAPH * D];
__device__ unsigned g_gmax[NGRAPH * D];
__device__ int      g_gcnt[NGRAPH];

// ---------------- init ----------------
__global__ void zero_kernel() {
    int i = blockIdx.x * blockDim.x + threadIdx.x;
    if (i < N_NODES) g_counts[i] = 0;
    if (i < NGRAPH * D) { g_gsum[i] = 0.f; g_gmax[i] = 0u; }
    if (i < NGRAPH) g_gcnt[i] = 0;
    if (i == 0) g_total = 0;
}

// ---------------- CSR build (bucket edges by dst) ----------------
__global__ void count_kernel(const int* __restrict__ ei) {
    int e = blockIdx.x * blockDim.x + threadIdx.x;
    if (e < N_EDGES) atomicAdd(&g_counts[ei[N_EDGES + e]], 1);
}

// segment-start assignment: warp-aggregated atomic (replaces serial scan)
__global__ void assign_kernel() {
    int i = blockIdx.x * blockDim.x + threadIdx.x;
    int lane = threadIdx.x & 31;
    int c = (i < N_NODES) ? g_counts[i] : 0;
    int pref = c;
#pragma unroll
    for (int off = 1; off < 32; off <<= 1) {
        int y = __shfl_up_sync(0xFFFFFFFF, pref, off);
        if (lane >= off) pref += y;
    }
    int total = __shfl_sync(0xFFFFFFFF, pref, 31);
    int base = 0;
    if (lane == 31) base = atomicAdd(&g_total, total);
    base = __shfl_sync(0xFFFFFFFF, base, 31);
    if (i < N_NODES) {
        int start = base + pref - c;
        g_offsets[i] = start;
        g_cursor[i]  = start;
    }
}

__global__ void fill_kernel(const int* __restrict__ ei) {
    int e = blockIdx.x * blockDim.x + threadIdx.x;
    if (e < N_EDGES) {
        int d = ei[N_EDGES + e];
        int p = atomicAdd(&g_cursor[d], 1);
        g_esrc[p] = ei[e];
    }
}

// ---------------- aggregation: g_z[i] = h[i] + sum_{CSR[i]} h[src] ----------
__global__ void agg_kernel(const float* __restrict__ xin, int sel) {
    const float* hin = (sel == 0) ? xin : ((sel == 1) ? g_hA : g_hB);
    int w    = (blockIdx.x * blockDim.x + threadIdx.x) >> 5;
    int lane = threadIdx.x & 31;
    if (w >= NPAD) return;
    float4 acc = make_float4(0.f, 0.f, 0.f, 0.f);
    if (w < N_NODES) {
        const float4* h4 = (const float4*)hin;
        acc = h4[(size_t)w * 32 + lane];
        int s = g_offsets[w];
        int e = s + g_counts[w];
        int j = s;
        for (; j + 4 <= e; j += 4) {
            int s0 = g_esrc[j], s1 = g_esrc[j + 1], s2 = g_esrc[j + 2], s3 = g_esrc[j + 3];
            float4 v0 = h4[(size_t)s0 * 32 + lane];
            float4 v1 = h4[(size_t)s1 * 32 + lane];
            float4 v2 = h4[(size_t)s2 * 32 + lane];
            float4 v3 = h4[(size_t)s3 * 32 + lane];
            acc.x += v0.x + v1.x + v2.x + v3.x;
            acc.y += v0.y + v1.y + v2.y + v3.y;
            acc.z += v0.z + v1.z + v2.z + v3.z;
            acc.w += v0.w + v1.w + v2.w + v3.w;
        }
        for (; j < e; j++) {
            int s0 = g_esrc[j];
            float4 v0 = h4[(size_t)s0 * 32 + lane];
            acc.x += v0.x; acc.y += v0.y; acc.z += v0.z; acc.w += v0.w;
        }
    }
    ((float4*)g_z)[(size_t)w * 32 + lane] = acc;
}

// ---------------- fp16-split tensor-core MLP (512 threads) ------------------
// hout = relu( relu(z @ W1) @ W2 ), 2-way fp16 split, 3 products (hh, hl, lh).
// 16 warps as 4x4 grid of 32x32 warp tiles.
// Row stride 68 u32 == 4 (mod 32) -> fragment LDS are bank-conflict-free.

#define STRH 136   // fp16 per row
#define STRW 68    // u32 per row
#define OFF_AH 0
#define OFF_AL (128 * STRH * 2)
#define OFF_BH (2 * 128 * STRH * 2)
#define OFF_BL (3 * 128 * STRH * 2)
#define SMEM_MLP (4 * 128 * STRH * 2)   // 139264 B

__device__ __forceinline__ void fsplit(float v, __half& hi, __half& lo) {
    hi = __float2half_rn(v);
    lo = __float2half_rn(v - __half2float(hi));
}
__device__ __forceinline__ unsigned pack2(__half a, __half b) {
    union { __half2 h; unsigned u; } q;
    q.h = __halves2half2(a, b);
    return q.u;
}
__device__ __forceinline__ void mma16(float c[4],
                                      unsigned a0, unsigned a1, unsigned a2, unsigned a3,
                                      unsigned b0, unsigned b1) {
    asm volatile(
        "mma.sync.aligned.m16n8k16.row.col.f32.f16.f16.f32 "
        "{%0,%1,%2,%3}, {%4,%5,%6,%7}, {%8,%9}, {%0,%1,%2,%3};"
        : "+f"(c[0]), "+f"(c[1]), "+f"(c[2]), "+f"(c[3])
        : "r"(a0), "r"(a1), "r"(a2), "r"(a3), "r"(b0), "r"(b1));
}

// 128x128x128: c += A(hi+lo) @ B(hi+lo)^T dropping lo*lo. Warp tile 32x32.
__device__ __forceinline__ void gemm128(const unsigned* __restrict__ Ah,
                                        const unsigned* __restrict__ Al,
                                        const unsigned* __restrict__ Bh,
                                        const unsigned* __restrict__ Bl,
                                        float c[2][4][4], int wm, int wn, int lane) {
    const int g = lane >> 2, tq = lane & 3;
#pragma unroll
    for (int ks = 0; ks < 8; ks++) {
        const int kq = ks * 8 + tq;           // u32 col index
        unsigned ah[2][4], al[2][4];
#pragma unroll
        for (int mf = 0; mf < 2; mf++) {
            int b = (wm * 32 + mf * 16 + g) * STRW + kq;
            ah[mf][0] = Ah[b];            ah[mf][1] = Ah[b + 8 * STRW];
            ah[mf][2] = Ah[b + 4];        ah[mf][3] = Ah[b + 8 * STRW + 4];
            al[mf][0] = Al[b];            al[mf][1] = Al[b + 8 * STRW];
            al[mf][2] = Al[b + 4];        al[mf][3] = Al[b + 8 * STRW + 4];
        }
        unsigned bh[4][2], bl[4][2];
#pragma unroll
        for (int nf = 0; nf < 4; nf++) {
            int b = (wn * 32 + nf * 8 + g) * STRW + kq;
            bh[nf][0] = Bh[b];  bh[nf][1] = Bh[b + 4];
            bl[nf][0] = Bl[b];  bl[nf][1] = Bl[b + 4];
        }
#pragma unroll
        for (int mf = 0; mf < 2; mf++)
#pragma unroll
            for (int nf = 0; nf < 4; nf++) {
                mma16(c[mf][nf], ah[mf][0], ah[mf][1], ah[mf][2], ah[mf][3],
                      bh[nf][0], bh[nf][1]);
                mma16(c[mf][nf], ah[mf][0], ah[mf][1], ah[mf][2], ah[mf][3],
                      bl[nf][0], bl[nf][1]);
                mma16(c[mf][nf], al[mf][0], al[mf][1], al[mf][2], al[mf][3],
                      bh[nf][0], bh[nf][1]);
            }
    }
}

// Transpose-split W[k][n] -> B[n][k] hi/lo. 512 threads.
__device__ __forceinline__ void load_w(const float* __restrict__ W,
                                       __half* Bh16, __half* Bl16, int tid) {
    const float4* wv = (const float4*)W;
#pragma unroll
    for (int i = 0; i < 8; i++) {
        int idx = tid + i * 512;
        int k = idx >> 5, n4 = (idx & 31) * 4;
        float4 v = wv[idx];
        __half h, l;
        fsplit(v.x, h, l); Bh16[(n4 + 0) * STRH + k] = h; Bl16[(n4 + 0) * STRH + k] = l;
        fsplit(v.y, h, l); Bh16[(n4 + 1) * STRH + k] = h; Bl16[(n4 + 1) * STRH + k] = l;
        fsplit(v.z, h, l); Bh16[(n4 + 2) * STRH + k] = h; Bl16[(n4 + 2) * STRH + k] = l;
        fsplit(v.w, h, l); Bh16[(n4 + 3) * STRH + k] = h; Bl16[(n4 + 3) * STRH + k] = l;
    }
}

__global__ __launch_bounds__(512)
void gin_mlp(const float* __restrict__ w1, const float* __restrict__ w2, int outsel) {
    extern __shared__ char smc[];
    unsigned* Ah = (unsigned*)(smc + OFF_AH);
    unsigned* Al = (unsigned*)(smc + OFF_AL);
    unsigned* Bh = (unsigned*)(smc + OFF_BH);
    unsigned* Bl = (unsigned*)(smc + OFF_BL);
    float* hout = (outsel == 1) ? g_hA : g_hB;
    const float* zin = g_z + (size_t)blockIdx.x * 128 * D;

    const int tid = threadIdx.x;
    const int lane = tid & 31;
    const int warp = tid >> 5;
    const int wm = warp >> 2, wn = warp & 3;
    const int g = lane >> 2, tq = lane & 3;

    // ---- split A (z tile) once ----
    {
        const float4* z4 = (const float4*)zin;
#pragma unroll
        for (int i = 0; i < 8; i++) {
            int idx = tid + i * 512;
            int r = idx >> 5, cu = (idx & 31) * 2;   // u32 col
            float4 v = z4[idx];
            __half h0, l0, h1, l1, h2, l2, h3, l3;
            fsplit(v.x, h0, l0); fsplit(v.y, h1, l1);
            fsplit(v.z, h2, l2); fsplit(v.w, h3, l3);
            Ah[r * STRW + cu]     = pack2(h0, h1);
            Ah[r * STRW + cu + 1] = pack2(h2, h3);
            Al[r * STRW + cu]     = pack2(l0, l1);
            Al[r * STRW + cu + 1] = pack2(l2, l3);
        }
    }
    load_w(w1, (__half*)Bh, (__half*)Bl, tid);
    __syncthreads();

    float c[2][4][4];
#pragma unroll
    for (int mf = 0; mf < 2; mf++)
#pragma unroll
        for (int nf = 0; nf < 4; nf++)
#pragma unroll
            for (int q = 0; q < 4; q++) c[mf][nf][q] = 0.f;

    gemm128(Ah, Al, Bh, Bl, c, wm, wn, lane);
    __syncthreads();

    // ---- t = relu(.) split straight back into Ah/Al; W2 into Bh/Bl ----
#pragma unroll
    for (int mf = 0; mf < 2; mf++)
#pragma unroll
        for (int nf = 0; nf < 4; nf++) {
            int r  = wm * 32 + mf * 16 + g;
            int cu = wn * 16 + nf * 4 + tq;          // u32 col of (c, c+1)
            float v0 = fmaxf(c[mf][nf][0], 0.f), v1 = fmaxf(c[mf][nf][1], 0.f);
            float v2 = fmaxf(c[mf][nf][2], 0.f), v3 = fmaxf(c[mf][nf][3], 0.f);
            __half h0, l0, h1, l1, h2, l2, h3, l3;
            fsplit(v0, h0, l0); fsplit(v1, h1, l1);
            fsplit(v2, h2, l2); fsplit(v3, h3, l3);
            Ah[r * STRW + cu]       = pack2(h0, h1);
            Al[r * STRW + cu]       = pack2(l0, l1);
            Ah[(r + 8) * STRW + cu] = pack2(h2, h3);
            Al[(r + 8) * STRW + cu] = pack2(l2, l3);
        }
    load_w(w2, (__half*)Bh, (__half*)Bl, tid);
    __syncthreads();

#pragma unroll
    for (int mf = 0; mf < 2; mf++)
#pragma unroll
        for (int nf = 0; nf < 4; nf++)
#pragma unroll
            for (int q = 0; q < 4; q++) c[mf][nf][q] = 0.f;

    gemm128(Ah, Al, Bh, Bl, c, wm, wn, lane);

    // ---- relu -> gmem ----
    const size_t row0 = (size_t)blockIdx.x * 128;
#pragma unroll
    for (int mf = 0; mf < 2; mf++)
#pragma unroll
        for (int nf = 0; nf < 4; nf++) {
            int r  = wm * 32 + mf * 16 + g;
            int cc = wn * 32 + nf * 8 + tq * 2;
            float2 o0, o1;
            o0.x = fmaxf(c[mf][nf][0], 0.f); o0.y = fmaxf(c[mf][nf][1], 0.f);
            o1.x = fmaxf(c[mf][nf][2], 0.f); o1.y = fmaxf(c[mf][nf][3], 0.f);
            *(float2*)&hout[(row0 + r) * D + cc]     = o0;
            *(float2*)&hout[(row0 + r + 8) * D + cc] = o1;
        }
}

// ---------------- pooling: segmented reduction exploiting sorted batch ----------
__global__ __launch_bounds__(128)
void pool_kernel(const int* __restrict__ batch) {
    int f = threadIdx.x;
    int n0 = blockIdx.x * 128;
    float s = 0.f, m = 0.f;
    int cur = -1, cnt = 0;
    for (int i = 0; i < 128; i++) {
        int n = n0 + i;
        if (n >= N_NODES) break;
        int gg = batch[n];
        if (gg != cur) {
            if (cur >= 0) {
                atomicAdd(&g_gsum[cur * D + f], s);
                atomicMax(&g_gmax[cur * D + f], __float_as_uint(m));  // h >= 0
                if (f == 0) atomicAdd(&g_gcnt[cur], cnt);
            }
            cur = gg; s = 0.f; m = 0.f; cnt = 0;
        }
        float v = g_hA[(size_t)n * D + f];
        s += v;
        m = fmaxf(m, v);
        cnt++;
    }
    if (cur >= 0) {
        atomicAdd(&g_gsum[cur * D + f], s);
        atomicMax(&g_gmax[cur * D + f], __float_as_uint(m));
        if (f == 0) atomicAdd(&g_gcnt[cur], cnt);
    }
}

// ---------------- readout: [gmax | gmean | gsum] @ out_w + out_b ----------------
__global__ void readout_kernel(const float* __restrict__ ow,
                               const float* __restrict__ ob,
                               float* __restrict__ out) {
    __shared__ float p[3 * D];
    int g = blockIdx.x;
    int o = threadIdx.x;
    if (o < D) {
        float s = g_gsum[g * D + o];
        float cn = fmaxf((float)g_gcnt[g], 1.f);
        p[o]         = __uint_as_float(g_gmax[g * D + o]);
        p[D + o]     = s / cn;
        p[2 * D + o] = s;
    }
    __syncthreads();
    float acc = ob[o];
#pragma unroll 8
    for (int f = 0; f < 3 * D; f++) acc = fmaf(p[f], ow[f * OUTF + o], acc);
    out[g * OUTF + o] = acc;
}

// ---------------- launch ----------------
extern "C" void kernel_launch(void* const* d_in, const int* in_sizes, int n_in,
                              void* d_out, int out_size) {
    const float* x      = (const float*)d_in[0];
    const int*   ei     = (const int*)  d_in[1];
    const int*   batch  = (const int*)  d_in[2];
    const float* w1_0   = (const float*)d_in[3];
    const float* w2_0   = (const float*)d_in[4];
    const float* gin_w1 = (const float*)d_in[5];   // [2][128][128]
    const float* gin_w2 = (const float*)d_in[6];
    const float* out_w  = (const float*)d_in[7];   // [384][256]
    const float* out_b  = (const float*)d_in[8];
    float* out = (float*)d_out;

    cudaFuncSetAttribute(gin_mlp,
                         cudaFuncAttributeMaxDynamicSharedMemorySize, SMEM_MLP);

    // init + CSR build (no serial scan; warp-aggregated atomic assignment)
    zero_kernel<<<(N_NODES + 255) / 256, 256>>>();
    count_kernel<<<(N_EDGES + 255) / 256, 256>>>(ei);
    assign_kernel<<<(N_NODES + 255) / 256, 256>>>();
    fill_kernel<<<(N_EDGES + 255) / 256, 256>>>(ei);

    const int AGG_BLOCKS = NPAD / 8;  // 8 warps/block, 1 warp/node

    // layer 0: x -> hA
    agg_kernel<<<AGG_BLOCKS, 256>>>(x, 0);
    gin_mlp<<<N_TILES, 512, SMEM_MLP>>>(w1_0, w2_0, 1);
    // layer 1: hA -> hB
    agg_kernel<<<AGG_BLOCKS, 256>>>(x, 1);
    gin_mlp<<<N_TILES, 512, SMEM_MLP>>>(gin_w1, gin_w2, 2);
    // layer 2: hB -> hA
    agg_kernel<<<AGG_BLOCKS, 256>>>(x, 2);
    gin_mlp<<<N_TILES, 512, SMEM_MLP>>>(gin_w1 + 128 * 128,
                                        gin_w2 + 128 * 128, 1);

    // pooling + readout
    pool_kernel<<<N_TILES, 128>>>(batch);
    readout_kernel<<<NGRAPH, 256>>>(out_w, out_b, out);
}

// round 8
// speedup vs baseline: 1.3317x; 1.0099x over previous
#include <cuda_runtime.h>
#include <cuda_fp16.h>
#include <cstdint>

// Problem constants (fixed by the dataset)
#define N_NODES 50000
#define NPAD    50048            // 391 * 128
#define N_EDGES 800000
#define D       128
#define NGRAPH  256
#define OUTF    256
#define N_TILES (NPAD / 128)     // 391

// ---------------- device scratch (no allocations allowed) ----------------
__device__ float    g_hA[(size_t)NPAD * D];
__device__ float    g_hB[(size_t)NPAD * D];
__device__ float    g_z [(size_t)NPAD * D];
__device__ int      g_counts [N_NODES];
__device__ int      g_offsets[N_NODES];      // segment starts (not monotonic)
__device__ int      g_cursor [N_NODES];
__device__ int      g_esrc   [N_EDGES];
__device__ int      g_total;
__device__ float    g_gsum[NGRAPH * D];
__device__ unsigned g_gmax[NGRAPH * D];
__device__ int      g_gcnt[NGRAPH];

// ---------------- init ----------------
__global__ void zero_kernel() {
    int i = blockIdx.x * blockDim.x + threadIdx.x;
    if (i < N_NODES) g_counts[i] = 0;
    if (i < NGRAPH * D) { g_gsum[i] = 0.f; g_gmax[i] = 0u; }
    if (i < NGRAPH) g_gcnt[i] = 0;
    if (i == 0) g_total = 0;
}

// ---------------- CSR build (bucket edges by dst) ----------------
__global__ void count_kernel(const int* __restrict__ ei) {
    int e = blockIdx.x * blockDim.x + threadIdx.x;
    if (e < N_EDGES) atomicAdd(&g_counts[ei[N_EDGES + e]], 1);
}

// segment-start assignment: warp-aggregated atomic (no serial scan)
__global__ void assign_kernel() {
    int i = blockIdx.x * blockDim.x + threadIdx.x;
    int lane = threadIdx.x & 31;
    int c = (i < N_NODES) ? g_counts[i] : 0;
    int pref = c;
#pragma unroll
    for (int off = 1; off < 32; off <<= 1) {
        int y = __shfl_up_sync(0xFFFFFFFF, pref, off);
        if (lane >= off) pref += y;
    }
    int total = __shfl_sync(0xFFFFFFFF, pref, 31);
    int base = 0;
    if (lane == 31) base = atomicAdd(&g_total, total);
    base = __shfl_sync(0xFFFFFFFF, base, 31);
    if (i < N_NODES) {
        int start = base + pref - c;
        g_offsets[i] = start;
        g_cursor[i]  = start;
    }
}

__global__ void fill_kernel(const int* __restrict__ ei) {
    int e = blockIdx.x * blockDim.x + threadIdx.x;
    if (e < N_EDGES) {
        int d = ei[N_EDGES + e];
        int p = atomicAdd(&g_cursor[d], 1);
        g_esrc[p] = ei[e];
    }
}

// ---------------- aggregation: g_z[i] = h[i] + sum_{CSR[i]} h[src] ----------
__global__ void agg_kernel(const float* __restrict__ xin, int sel) {
    const float* hin = (sel == 0) ? xin : ((sel == 1) ? g_hA : g_hB);
    int w    = (blockIdx.x * blockDim.x + threadIdx.x) >> 5;
    int lane = threadIdx.x & 31;
    if (w >= NPAD) return;
    float4 acc = make_float4(0.f, 0.f, 0.f, 0.f);
    if (w < N_NODES) {
        const float4* h4 = (const float4*)hin;
        acc = h4[(size_t)w * 32 + lane];
        int s = g_offsets[w];
        int e = s + g_counts[w];
        int j = s;
        for (; j + 4 <= e; j += 4) {
            int s0 = g_esrc[j], s1 = g_esrc[j + 1], s2 = g_esrc[j + 2], s3 = g_esrc[j + 3];
            float4 v0 = h4[(size_t)s0 * 32 + lane];
            float4 v1 = h4[(size_t)s1 * 32 + lane];
            float4 v2 = h4[(size_t)s2 * 32 + lane];
            float4 v3 = h4[(size_t)s3 * 32 + lane];
            acc.x += v0.x + v1.x + v2.x + v3.x;
            acc.y += v0.y + v1.y + v2.y + v3.y;
            acc.z += v0.z + v1.z + v2.z + v3.z;
            acc.w += v0.w + v1.w + v2.w + v3.w;
        }
        for (; j < e; j++) {
            int s0 = g_esrc[j];
            float4 v0 = h4[(size_t)s0 * 32 + lane];
            acc.x += v0.x; acc.y += v0.y; acc.z += v0.z; acc.w += v0.w;
        }
    }
    ((float4*)g_z)[(size_t)w * 32 + lane] = acc;
}

// ---------------- fp16-split tensor-core MLP, 2 CTAs/SM ---------------------
// hout = relu( relu(z @ W1) @ W2 ), 2-way fp16 split, 3 products (hh, hl, lh).
// 256 threads = 8 warps as 2x4 grid of 64x32 warp tiles.
// A (hi/lo, full 128x128) resident; B staged per K=64 half (2 halves/GEMM).
// SMEM/CTA = 106496 B -> 2 CTAs/SM. Strides 68/36 u32 (==4 mod 32, conflict-free).

#define ASTR 68    // A row stride in u32 (136 halves)
#define BSTR 36    // B row stride in u32 (72 halves, 32 used)
#define OFF_AH 0
#define OFF_AL (128 * ASTR * 4)             // 34816
#define OFF_BH (2 * 128 * ASTR * 4)         // 69632
#define OFF_BL (OFF_BH + 128 * BSTR * 4)    // 88064
#define SMEM_MLP (OFF_BL + 128 * BSTR * 4)  // 106496

__device__ __forceinline__ void fsplit(float v, __half& hi, __half& lo) {
    hi = __float2half_rn(v);
    lo = __float2half_rn(v - __half2float(hi));
}
__device__ __forceinline__ unsigned pack2(__half a, __half b) {
    union { __half2 h; unsigned u; } q;
    q.h = __halves2half2(a, b);
    return q.u;
}
__device__ __forceinline__ void mma16(float c[4],
                                      unsigned a0, unsigned a1, unsigned a2, unsigned a3,
                                      unsigned b0, unsigned b1) {
    asm volatile(
        "mma.sync.aligned.m16n8k16.row.col.f32.f16.f16.f32 "
        "{%0,%1,%2,%3}, {%4,%5,%6,%7}, {%8,%9}, {%0,%1,%2,%3};"
        : "+f"(c[0]), "+f"(c[1]), "+f"(c[2]), "+f"(c[3])
        : "r"(a0), "r"(a1), "r"(a2), "r"(a3), "r"(b0), "r"(b1));
}

// K=64 half-GEMM: c += A(hi+lo)[:, half] @ B(hi+lo)^T dropping lo*lo.
// Warp tile 64x32 (4 mf x 4 nf fragments).
__device__ __forceinline__ void gemm_half(const unsigned* __restrict__ Ah,
                                          const unsigned* __restrict__ Al,
                                          const unsigned* __restrict__ Bh,
                                          const unsigned* __restrict__ Bl,
                                          float c[4][4][4], int wm, int wn,
                                          int lane, int half) {
    const int g = lane >> 2, tq = lane & 3;
#pragma unroll
    for (int ks = 0; ks < 4; ks++) {
        const int kqa = half * 32 + ks * 8 + tq;   // u32 col in A
        const int kqb = ks * 8 + tq;               // u32 col in B half
        unsigned ah[4][4], al[4][4];
#pragma unroll
        for (int mf = 0; mf < 4; mf++) {
            int b = (wm * 64 + mf * 16 + g) * ASTR + kqa;
            ah[mf][0] = Ah[b];            ah[mf][1] = Ah[b + 8 * ASTR];
            ah[mf][2] = Ah[b + 4];        ah[mf][3] = Ah[b + 8 * ASTR + 4];
            al[mf][0] = Al[b];            al[mf][1] = Al[b + 8 * ASTR];
            al[mf][2] = Al[b + 4];        al[mf][3] = Al[b + 8 * ASTR + 4];
        }
        unsigned bh[4][2], bl[4][2];
#pragma unroll
        for (int nf = 0; nf < 4; nf++) {
            int b = (wn * 32 + nf * 8 + g) * BSTR + kqb;
            bh[nf][0] = Bh[b];  bh[nf][1] = Bh[b + 4];
            bl[nf][0] = Bl[b];  bl[nf][1] = Bl[b + 4];
        }
#pragma unroll
        for (int mf = 0; mf < 4; mf++)
#pragma unroll
            for (int nf = 0; nf < 4; nf++) {
                mma16(c[mf][nf], ah[mf][0], ah[mf][1], ah[mf][2], ah[mf][3],
                      bh[nf][0], bh[nf][1]);
                mma16(c[mf][nf], ah[mf][0], ah[mf][1], ah[mf][2], ah[mf][3],
                      bl[nf][0], bl[nf][1]);
                mma16(c[mf][nf], al[mf][0], al[mf][1], al[mf][2], al[mf][3],
                      bh[nf][0], bh[nf][1]);
            }
    }
}

// Transpose-split one K=64 half of W[k][n] -> B[n][k] hi/lo. 256 threads.
__device__ __forceinline__ void load_w_half(const float* __restrict__ W,
                                            __half* Bh16, __half* Bl16,
                                            int tid, int half) {
    const float4* wv = (const float4*)W;
#pragma unroll
    for (int i = 0; i < 8; i++) {
        int idx = tid + i * 256;                  // 2048 float4 = 64 k x 32 n4
        int k = idx >> 5, n4 = (idx & 31) * 4;
        float4 v = wv[(half * 64 + k) * 32 + (idx & 31)];
        __half h, l;
        fsplit(v.x, h, l); Bh16[(n4 + 0) * 2 * BSTR + k] = h; Bl16[(n4 + 0) * 2 * BSTR + k] = l;
        fsplit(v.y, h, l); Bh16[(n4 + 1) * 2 * BSTR + k] = h; Bl16[(n4 + 1) * 2 * BSTR + k] = l;
        fsplit(v.z, h, l); Bh16[(n4 + 2) * 2 * BSTR + k] = h; Bl16[(n4 + 2) * 2 * BSTR + k] = l;
        fsplit(v.w, h, l); Bh16[(n4 + 3) * 2 * BSTR + k] = h; Bl16[(n4 + 3) * 2 * BSTR + k] = l;
    }
}

__global__ __launch_bounds__(256, 2)
void gin_mlp(const float* __restrict__ w1, const float* __restrict__ w2, int outsel) {
    extern __shared__ char smc[];
    unsigned* Ah = (unsigned*)(smc + OFF_AH);
    unsigned* Al = (unsigned*)(smc + OFF_AL);
    unsigned* Bh = (unsigned*)(smc + OFF_BH);
    unsigned* Bl = (unsigned*)(smc + OFF_BL);
    float* hout = (outsel == 1) ? g_hA : g_hB;
    const float* zin = g_z + (size_t)blockIdx.x * 128 * D;

    const int tid = threadIdx.x;
    const int lane = tid & 31;
    const int warp = tid >> 5;
    const int wm = warp >> 2, wn = warp & 3;
    const int g = lane >> 2, tq = lane & 3;

    // ---- split A (z tile) once, full 128x128 ----
    {
        const float4* z4 = (const float4*)zin;
#pragma unroll
        for (int i = 0; i < 16; i++) {
            int idx = tid + i * 256;
            int r = idx >> 5, cu = (idx & 31) * 2;   // u32 col
            float4 v = z4[idx];
            __half h0, l0, h1, l1, h2, l2, h3, l3;
            fsplit(v.x, h0, l0); fsplit(v.y, h1, l1);
            fsplit(v.z, h2, l2); fsplit(v.w, h3, l3);
            Ah[r * ASTR + cu]     = pack2(h0, h1);
            Ah[r * ASTR + cu + 1] = pack2(h2, h3);
            Al[r * ASTR + cu]     = pack2(l0, l1);
            Al[r * ASTR + cu + 1] = pack2(l2, l3);
        }
    }

    float c[4][4][4];

    // ==== GEMM 1: t = relu(z @ W1), K processed in two 64-halves ====
#pragma unroll
    for (int mf = 0; mf < 4; mf++)
#pragma unroll
        for (int nf = 0; nf < 4; nf++)
#pragma unroll
            for (int q = 0; q < 4; q++) c[mf][nf][q] = 0.f;

#pragma unroll
    for (int half = 0; half < 2; half++) {
        load_w_half(w1, (__half*)Bh, (__half*)Bl, tid, half);
        __syncthreads();
        gemm_half(Ah, Al, Bh, Bl, c, wm, wn, lane, half);
        __syncthreads();
    }

    // ---- t = relu(.) split back into Ah/Al ----
#pragma unroll
    for (int mf = 0; mf < 4; mf++)
#pragma unroll
        for (int nf = 0; nf < 4; nf++) {
            int r  = wm * 64 + mf * 16 + g;
            int cu = wn * 16 + nf * 4 + tq;          // u32 col of (c, c+1)
            float v0 = fmaxf(c[mf][nf][0], 0.f), v1 = fmaxf(c[mf][nf][1], 0.f);
            float v2 = fmaxf(c[mf][nf][2], 0.f), v3 = fmaxf(c[mf][nf][3], 0.f);
            __half h0, l0, h1, l1, h2, l2, h3, l3;
            fsplit(v0, h0, l0); fsplit(v1, h1, l1);
            fsplit(v2, h2, l2); fsplit(v3, h3, l3);
            Ah[r * ASTR + cu]       = pack2(h0, h1);
            Al[r * ASTR + cu]       = pack2(l0, l1);
            Ah[(r + 8) * ASTR + cu] = pack2(h2, h3);
            Al[(r + 8) * ASTR + cu] = pack2(l2, l3);
        }
    __syncthreads();

    // ==== GEMM 2: out = relu(t @ W2) ====
#pragma unroll
    for (int mf = 0; mf < 4; mf++)
#pragma unroll
        for (int nf = 0; nf < 4; nf++)
#pragma unroll
            for (int q = 0; q < 4; q++) c[mf][nf][q] = 0.f;

#pragma unroll
    for (int half = 0; half < 2; half++) {
        load_w_half(w2, (__half*)Bh, (__half*)Bl, tid, half);
        __syncthreads();
        gemm_half(Ah, Al, Bh, Bl, c, wm, wn, lane, half);
        __syncthreads();
    }

    // ---- relu -> gmem ----
    const size_t row0 = (size_t)blockIdx.x * 128;
#pragma unroll
    for (int mf = 0; mf < 4; mf++)
#pragma unroll
        for (int nf = 0; nf < 4; nf++) {
            int r  = wm * 64 + mf * 16 + g;
            int cc = wn * 32 + nf * 8 + tq * 2;
            float2 o0, o1;
            o0.x = fmaxf(c[mf][nf][0], 0.f); o0.y = fmaxf(c[mf][nf][1], 0.f);
            o1.x = fmaxf(c[mf][nf][2], 0.f); o1.y = fmaxf(c[mf][nf][3], 0.f);
            *(float2*)&hout[(row0 + r) * D + cc]     = o0;
            *(float2*)&hout[(row0 + r + 8) * D + cc] = o1;
        }
}

// ---------------- pooling: segmented reduction exploiting sorted batch ----------
__global__ __launch_bounds__(128)
void pool_kernel(const int* __restrict__ batch) {
    int f = threadIdx.x;
    int n0 = blockIdx.x * 128;
    float s = 0.f, m = 0.f;
    int cur = -1, cnt = 0;
    for (int i = 0; i < 128; i++) {
        int n = n0 + i;
        if (n >= N_NODES) break;
        int gg = batch[n];
        if (gg != cur) {
            if (cur >= 0) {
                atomicAdd(&g_gsum[cur * D + f], s);
                atomicMax(&g_gmax[cur * D + f], __float_as_uint(m));  // h >= 0
                if (f == 0) atomicAdd(&g_gcnt[cur], cnt);
            }
            cur = gg; s = 0.f; m = 0.f; cnt = 0;
        }
        float v = g_hA[(size_t)n * D + f];
        s += v;
        m = fmaxf(m, v);
        cnt++;
    }
    if (cur >= 0) {
        atomicAdd(&g_gsum[cur * D + f], s);
        atomicMax(&g_gmax[cur * D + f], __float_as_uint(m));
        if (f == 0) atomicAdd(&g_gcnt[cur], cnt);
    }
}

// ---------------- readout: [gmax | gmean | gsum] @ out_w + out_b ----------------
__global__ void readout_kernel(const float* __restrict__ ow,
                               const float* __restrict__ ob,
                               float* __restrict__ out) {
    __shared__ float p[3 * D];
    int g = blockIdx.x;
    int o = threadIdx.x;
    if (o < D) {
        float s = g_gsum[g * D + o];
        float cn = fmaxf((float)g_gcnt[g], 1.f);
        p[o]         = __uint_as_float(g_gmax[g * D + o]);
        p[D + o]     = s / cn;
        p[2 * D + o] = s;
    }
    __syncthreads();
    float acc = ob[o];
#pragma unroll 8
    for (int f = 0; f < 3 * D; f++) acc = fmaf(p[f], ow[f * OUTF + o], acc);
    out[g * OUTF + o] = acc;
}

// ---------------- launch ----------------
extern "C" void kernel_launch(void* const* d_in, const int* in_sizes, int n_in,
                              void* d_out, int out_size) {
    const float* x      = (const float*)d_in[0];
    const int*   ei     = (const int*)  d_in[1];
    const int*   batch  = (const int*)  d_in[2];
    const float* w1_0   = (const float*)d_in[3];
    const float* w2_0   = (const float*)d_in[4];
    const float* gin_w1 = (const float*)d_in[5];   // [2][128][128]
    const float* gin_w2 = (const float*)d_in[6];
    const float* out_w  = (const float*)d_in[7];   // [384][256]
    const float* out_b  = (const float*)d_in[8];
    float* out = (float*)d_out;

    cudaFuncSetAttribute(gin_mlp,
                         cudaFuncAttributeMaxDynamicSharedMemorySize, SMEM_MLP);

    // init + CSR build (no serial scan; warp-aggregated atomic assignment)
    zero_kernel<<<(N_NODES + 255) / 256, 256>>>();
    count_kernel<<<(N_EDGES + 255) / 256, 256>>>(ei);
    assign_kernel<<<(N_NODES + 255) / 256, 256>>>();
    fill_kernel<<<(N_EDGES + 255) / 256, 256>>>(ei);

    const int AGG_BLOCKS = NPAD / 8;  // 8 warps/block, 1 warp/node

    // layer 0: x -> hA
    agg_kernel<<<AGG_BLOCKS, 256>>>(x, 0);
    gin_mlp<<<N_TILES, 256, SMEM_MLP>>>(w1_0, w2_0, 1);
    // layer 1: hA -> hB
    agg_kernel<<<AGG_BLOCKS, 256>>>(x, 1);
    gin_mlp<<<N_TILES, 256, SMEM_MLP>>>(gin_w1, gin_w2, 2);
    // layer 2: hB -> hA
    agg_kernel<<<AGG_BLOCKS, 256>>>(x, 2);
    gin_mlp<<<N_TILES, 256, SMEM_MLP>>>(gin_w1 + 128 * 128,
                                        gin_w2 + 128 * 128, 1);

    // pooling + readout
    pool_kernel<<<N_TILES, 128>>>(batch);
    readout_kernel<<<NGRAPH, 256>>>(out_w, out_b, out);
}